// round 10
// baseline (speedup 1.0000x reference)
#include <cuda_runtime.h>

// ---------------------------------------------------------------------------
// PC_RNN_HC_A round 9: 256 CTAs (2/SM, 16 warps/SM), prefetch-before-barrier,
// FFMA2 packed math, cp.async double buffering, broadcast-LDG A operand.
// ---------------------------------------------------------------------------

#define GRID      256
#define NTHREADS  256

#define SEQ   512
#define BATCH 256
#define OUTD  256
#define CAUS  64
#define HID   512

#define SB 68          // conflict-free smem stride (see R7/R8)
#define WC_OFF (2 * 32 * SB)   // third smem slot for the w_c tile

typedef unsigned long long u64;

// Persistent state (device globals; allocation forbidden)
__device__ float g_h  [BATCH * HID];
__device__ float g_th [BATCH * HID];
__device__ float g_hp [BATCH * HID];
__device__ float g_tp [BATCH * HID];
__device__ float g_eh [BATCH * HID];
__device__ float g_err[BATCH * OUTD];
__device__ float g_c  [BATCH * CAUS];
__device__ float g_woT[HID * OUTD];   // woT[i][o] = w_o[o][i]
__device__ float g_wcT[CAUS * HID];   // wcT[c][i] = w_c[i][c]

__device__ unsigned g_bar_count;      // zero at module load
__device__ unsigned g_bar_gen;

// ---------------------------------------------------------------------------
// Grid barrier core. Call AFTER __syncthreads() (and optional prefetch issue).
// Monotone generation -> replay-safe. All 256 CTAs resident (2/SM) -> no
// deadlock.
// ---------------------------------------------------------------------------
__device__ __forceinline__ void barrier_core() {
    if (threadIdx.x == 0) {
        volatile unsigned* genp = &g_bar_gen;
        unsigned my = *genp;
        __threadfence();
        unsigned prev = atomicAdd(&g_bar_count, 1u);
        if (prev == GRID - 1u) {
            g_bar_count = 0u;
            __threadfence();
            atomicExch(&g_bar_gen, my + 1u);
        } else {
            while (*genp == my) { }
            __threadfence();
        }
    }
    __syncthreads();
}

// ---------------------------------------------------------------------------
// Packed f32x2 FMA (SASS FFMA2; PTX-only form)
// ---------------------------------------------------------------------------
__device__ __forceinline__ void ffma2(u64 &acc, u64 a, u64 b) {
    asm("fma.rn.f32x2 %0, %1, %2, %0;" : "+l"(acc) : "l"(a), "l"(b));
}
__device__ __forceinline__ float fsum2(u64 v) {
    float lo, hi;
    asm("mov.b64 {%0,%1}, %2;" : "=f"(lo), "=f"(hi) : "l"(v));
    return lo + hi;
}

// ---------------------------------------------------------------------------
// cp.async helpers
// ---------------------------------------------------------------------------
__device__ __forceinline__ void cp_async16(float* s, const float* g) {
    unsigned sa = (unsigned)__cvta_generic_to_shared(s);
    asm volatile("cp.async.ca.shared.global [%0], [%1], 16;" :: "r"(sa), "l"(g));
}
__device__ __forceinline__ void cp_commit() { asm volatile("cp.async.commit_group;"); }
__device__ __forceinline__ void cp_wait0()  { asm volatile("cp.async.wait_group 0;"); }

// Fill one B tile: TN rows x 64 k, k-major source (leading dim ldb).
template<int TN>
__device__ __forceinline__ void fill_b(float* bs, const float* __restrict__ B,
                                       int ldb, int k0) {
    const int tid = threadIdx.x;
#pragma unroll
    for (int it = 0; it < (TN * 16) / NTHREADS; it++) {
        int idx = tid + it * NTHREADS;
        int n   = idx >> 4;
        int k4  = idx & 15;
        cp_async16(bs + n * SB + k4 * 4, B + n * ldb + k0 + k4 * 4);
    }
}

// ---------------------------------------------------------------------------
// NT GEMM, RM=1, prefilled: buffer 0 already holds k-tile 0 (committed before
// the preceding grid barrier). A row read straight from global (warp-broadcast:
// 2 distinct addresses per warp-LDG). accP[in] packed f32x2.
// ---------------------------------------------------------------------------
template<int RN>
__device__ __forceinline__ void gemm_pref(float* bbuf,
                                          const float* __restrict__ A, int lda,
                                          const float* __restrict__ B, int ldb,
                                          int ktiles,
                                          u64 (&accP)[RN]) {
    constexpr int TN = 16 * RN;
    const int tx = threadIdx.x & 15;
    const int ty = threadIdx.x >> 4;
    const float* Ar = A + ty * lda;

    int buf = 0;
    for (int kt = 0; kt < ktiles; kt++) {
        cp_wait0();
        __syncthreads();
        if (kt + 1 < ktiles) {
            fill_b<TN>(bbuf + (buf ^ 1) * TN * SB, B, ldb, (kt + 1) * 64);
            cp_commit();
        }
        const float* bs = bbuf + buf * TN * SB;
        const int kb = kt * 64;
#pragma unroll
        for (int k4 = 0; k4 < 16; k4++) {
            ulonglong2 a2 = *reinterpret_cast<const ulonglong2*>(Ar + kb + k4 * 4);
#pragma unroll
            for (int in = 0; in < RN; in++) {
                ulonglong2 b2 = *reinterpret_cast<const ulonglong2*>(
                    bs + (tx + 16 * in) * SB + k4 * 4);
                ffma2(accP[in], a2.x, b2.x);
                ffma2(accP[in], a2.y, b2.y);
            }
        }
        buf ^= 1;
    }
}

// ---------------------------------------------------------------------------
// Main persistent kernel (2 CTAs/SM)
// ---------------------------------------------------------------------------
__global__ void __launch_bounds__(NTHREADS, 2)
pc_rnn_kernel(const float* __restrict__ x,
              const float* __restrict__ c_init,
              const float* __restrict__ h_init,
              const float* __restrict__ w_o,
              const float* __restrict__ b_o,
              const float* __restrict__ w_c,
              const float* __restrict__ w_r,
              const float* __restrict__ b_r,
              float* __restrict__ out) {
    __shared__ float bbuf[3 * 32 * SB];   // dbl buffer (2x 32-row) + w_c slot

    const int bid = blockIdx.x;
    const int tid = threadIdx.x;
    const int tx  = tid & 15, ty = tid >> 4;
    const int gtid = bid * NTHREADS + tid;
    const int gstride = GRID * NTHREADS;

    // Tile maps (256 CTAs)
    const int rowA = (bid >> 4) * 16, colA = (bid & 15) * 32;  // A/C: 16x32
    const int rowB = (bid >> 4) * 16, colB = (bid & 15) * 16;  // B:   16x16
    const int rowD = (bid >> 2) * 8,  colD = (bid & 3) * 16;   // D (bid<128): 8x16

    // ---- init state + weight transposes (fresh every launch/replay) ----
    for (int i = gtid; i < BATCH * HID; i += gstride) {
        float h = h_init[i];
        g_h[i]  = h;
        g_th[i] = tanhf(h);
    }
    for (int i = gtid; i < BATCH * CAUS; i += gstride)
        g_c[i] = c_init[i];
    for (int i = gtid; i < HID * OUTD; i += gstride) {   // woT[i][o] = w_o[o][i]
        int hh = i >> 8, o = i & (OUTD - 1);
        g_woT[i] = w_o[o * HID + hh];
    }
    for (int i = gtid; i < CAUS * HID; i += gstride) {   // wcT[c][i] = w_c[i][c]
        int c = i >> 9, hh = i & (HID - 1);
        g_wcT[i] = w_c[hh * CAUS + c];
    }
    __syncthreads();
    // prefetch phase-A weights (static) before the init barrier
    fill_b<32>(bbuf, w_r + colA * HID, HID, 0);
    fill_b<32>(bbuf + WC_OFF, w_c + colA * CAUS, CAUS, 0);
    cp_commit();
    barrier_core();

    for (int t = 0; t < SEQ; t++) {
        // ---- Phase A: h_prior = 0.9*h + 0.1*(th@Wr^T + c@Wc^T + b_r); tp ----
        {
            u64 acc[2] = {0ull, 0ull};
            gemm_pref<2>(bbuf, g_th + rowA * HID, HID,
                         w_r + colA * HID, HID, HID / 64, acc);
            // c @ Wc^T part: single k-tile, already resident in WC_OFF slot
            {
                const float* Ar = g_c + (rowA + ty) * CAUS;
                const float* bs = bbuf + WC_OFF;
#pragma unroll
                for (int k4 = 0; k4 < 16; k4++) {
                    ulonglong2 a2 = *reinterpret_cast<const ulonglong2*>(Ar + k4 * 4);
#pragma unroll
                    for (int in = 0; in < 2; in++) {
                        ulonglong2 b2 = *reinterpret_cast<const ulonglong2*>(
                            bs + (tx + 16 * in) * SB + k4 * 4);
                        ffma2(acc[in], a2.x, b2.x);
                        ffma2(acc[in], a2.y, b2.y);
                    }
                }
            }
            const int r = rowA + ty;
#pragma unroll
            for (int in = 0; in < 2; in++) {
                int ci  = colA + tx + 16 * in;
                int idx = r * HID + ci;
                float hp = 0.9f * g_h[idx] + 0.1f * (fsum2(acc[in]) + b_r[ci]);
                g_hp[idx] = hp;
                g_tp[idx] = tanhf(hp);
            }
        }
        __syncthreads();
        fill_b<16>(bbuf, w_o + colB * HID, HID, 0);   // prefetch phase-B weights
        cp_commit();
        barrier_core();

        // ---- Phase B: err = tp@Wo^T + b_o - x_t  (streamed to out too) ----
        {
            u64 acc[1] = {0ull};
            gemm_pref<1>(bbuf, g_tp + rowB * HID, HID,
                         w_o + colB * HID, HID, HID / 64, acc);
            const int r  = rowB + ty;
            const int o  = colB + tx;
            const int xi = (t * BATCH + r) * OUTD + o;
            float e = fsum2(acc[0]) + b_o[o] - x[xi];
            g_err[r * OUTD + o] = e;
            out[xi] = e;
        }
        __syncthreads();
        fill_b<32>(bbuf, g_woT + colA * OUTD, OUTD, 0);  // prefetch phase-C weights
        cp_commit();
        barrier_core();

        // ---- Phase C: g = err@woT; eh = 0.1*(1-tp^2)*g; h_post; th ----
        {
            u64 acc[2] = {0ull, 0ull};
            gemm_pref<2>(bbuf, g_err + rowA * OUTD, OUTD,
                         g_woT + colA * OUTD, OUTD, OUTD / 64, acc);
            const int r = rowA + ty;
#pragma unroll
            for (int in = 0; in < 2; in++) {
                int ci  = colA + tx + 16 * in;
                int idx = r * HID + ci;
                float tp = g_tp[idx];
                float eh = 0.1f * (1.0f - tp * tp) * fsum2(acc[in]);
                float hpost = g_hp[idx] - eh;
                g_eh[idx] = eh;
                g_h[idx]  = hpost;
                g_th[idx] = tanhf(hpost);
            }
        }
        __syncthreads();
        if (bid < 128) {                                  // prefetch phase-D weights
            fill_b<16>(bbuf, g_wcT + colD * HID, HID, 0);
            cp_commit();
        }
        barrier_core();

        // ---- Phase D: c -= 0.1 * (eh @ Wc)  (via wcT; 128 working CTAs) ----
        if (bid < 128) {
            const bool act = (tid < 128);
            const int r = rowD + (ty & 7);
            const float* Arow = g_eh + r * HID;
            const float* Bp   = g_wcT + colD * HID;
            u64 accD = 0ull;
            int buf = 0;
            for (int kt = 0; kt < 8; kt++) {
                cp_wait0();
                __syncthreads();
                if (kt < 7) {
                    fill_b<16>(bbuf + (buf ^ 1) * 16 * SB, Bp, HID, (kt + 1) * 64);
                    cp_commit();
                }
                if (act) {
                    const float* bs = bbuf + buf * 16 * SB;
                    const int kb = kt * 64;
#pragma unroll
                    for (int k4 = 0; k4 < 16; k4++) {
                        ulonglong2 a = *reinterpret_cast<const ulonglong2*>(Arow + kb + k4 * 4);
                        ulonglong2 b = *reinterpret_cast<const ulonglong2*>(bs + tx * SB + k4 * 4);
                        ffma2(accD, a.x, b.x);
                        ffma2(accD, a.y, b.y);
                    }
                }
                buf ^= 1;
            }
            if (act)
                g_c[r * CAUS + colD + tx] -= 0.1f * fsum2(accD);
        }
        __syncthreads();
        fill_b<32>(bbuf, w_r + colA * HID, HID, 0);       // prefetch next step's A
        fill_b<32>(bbuf + WC_OFF, w_c + colA * CAUS, CAUS, 0);
        cp_commit();
        barrier_core();
    }
}

// ---------------------------------------------------------------------------
// Launch: single graph-capturable kernel node, no allocation.
// Inputs (metadata order): x, c_init, h_init, w_o, b_o, w_c, w_r, b_r
// ---------------------------------------------------------------------------
extern "C" void kernel_launch(void* const* d_in, const int* in_sizes, int n_in,
                              void* d_out, int out_size) {
    const float* x      = (const float*)d_in[0];
    const float* c_init = (const float*)d_in[1];
    const float* h_init = (const float*)d_in[2];
    const float* w_o    = (const float*)d_in[3];
    const float* b_o    = (const float*)d_in[4];
    const float* w_c    = (const float*)d_in[5];
    const float* w_r    = (const float*)d_in[6];
    const float* b_r    = (const float*)d_in[7];
    float* out = (float*)d_out;

    pc_rnn_kernel<<<GRID, NTHREADS>>>(x, c_init, h_init, w_o, b_o, w_c, w_r, b_r, out);
}

// round 13
// speedup vs baseline: 1.4687x; 1.4687x over previous
#include <cuda_runtime.h>

// ---------------------------------------------------------------------------
// PC_RNN_HC_A round 10: 128 CTAs (1/SM), BOTH GEMM operands staged through
// cp.async double-buffered smem (kills exposed L2 latency on activations),
// FFMA2 packed math, prefetch-before-barrier for static weights.
// ---------------------------------------------------------------------------

#define GRID      128
#define NTHREADS  256

#define SEQ   512
#define BATCH 256
#define OUTD  256
#define CAUS  64
#define HID   512

#define SB 68             // conflict-free smem row stride (floats)
#define BUFSZ (32 * SB)   // one buffer = up to 32 rows

typedef unsigned long long u64;

// Persistent state (device globals; allocation forbidden)
__device__ float g_h  [BATCH * HID];
__device__ float g_th [BATCH * HID];
__device__ float g_hp [BATCH * HID];
__device__ float g_tp [BATCH * HID];
__device__ float g_eh [BATCH * HID];
__device__ float g_err[BATCH * OUTD];
__device__ float g_c  [BATCH * CAUS];
__device__ float g_woT[HID * OUTD];   // woT[i][o] = w_o[o][i]
__device__ float g_wcT[CAUS * HID];   // wcT[c][i] = w_c[i][c]

__device__ unsigned g_bar_count;      // zero at module load
__device__ unsigned g_bar_gen;

// ---------------------------------------------------------------------------
// Grid barrier (monotone generation; replay-safe; 128 CTAs <= #SMs).
// ---------------------------------------------------------------------------
__device__ __forceinline__ void barrier_core() {
    if (threadIdx.x == 0) {
        volatile unsigned* genp = &g_bar_gen;
        unsigned my = *genp;
        __threadfence();
        unsigned prev = atomicAdd(&g_bar_count, 1u);
        if (prev == GRID - 1u) {
            g_bar_count = 0u;
            __threadfence();
            atomicExch(&g_bar_gen, my + 1u);
        } else {
            while (*genp == my) { }
            __threadfence();
        }
    }
    __syncthreads();
}

// ---------------------------------------------------------------------------
// Packed f32x2 FMA (SASS FFMA2; PTX-only form)
// ---------------------------------------------------------------------------
__device__ __forceinline__ void ffma2(u64 &acc, u64 a, u64 b) {
    asm("fma.rn.f32x2 %0, %1, %2, %0;" : "+l"(acc) : "l"(a), "l"(b));
}
__device__ __forceinline__ float fsum2(u64 v) {
    float lo, hi;
    asm("mov.b64 {%0,%1}, %2;" : "=f"(lo), "=f"(hi) : "l"(v));
    return lo + hi;
}

// ---------------------------------------------------------------------------
// cp.async helpers
// ---------------------------------------------------------------------------
__device__ __forceinline__ void cp_async16(float* s, const float* g) {
    unsigned sa = (unsigned)__cvta_generic_to_shared(s);
    asm volatile("cp.async.ca.shared.global [%0], [%1], 16;" :: "r"(sa), "l"(g));
}
__device__ __forceinline__ void cp_commit() { asm volatile("cp.async.commit_group;"); }
__device__ __forceinline__ void cp_wait0()  { asm volatile("cp.async.wait_group 0;"); }

// Fill a TR-row x 64-k tile from k-major source (leading dim ldb).
template<int TR>
__device__ __forceinline__ void fill_t(float* s, const float* __restrict__ B,
                                       int ldb, int k0) {
    const int tid = threadIdx.x;
    constexpr int TOT = TR * 16;
    if (TOT >= NTHREADS) {
#pragma unroll
        for (int it = 0; it < TOT / NTHREADS; it++) {
            int idx = tid + it * NTHREADS;
            int n = idx >> 4, k4 = idx & 15;
            cp_async16(s + n * SB + k4 * 4, B + n * ldb + k0 + k4 * 4);
        }
    } else if (tid < TOT) {
        int n = tid >> 4, k4 = tid & 15;
        cp_async16(s + n * SB + k4 * 4, B + n * ldb + k0 + k4 * 4);
    }
}

// ---------------------------------------------------------------------------
// Smem-smem NT GEMM. Precondition: B k-tile 0 already cp.async-committed into
// sb buffer 0 (issued before the preceding grid barrier). A k-tile 0 is filled
// here. Both operands double-buffered; compute is pure LDS + FFMA2.
// ---------------------------------------------------------------------------
template<int RM, int RN>
__device__ __forceinline__ void gemm_ss(float* sa, float* sb,
                                        const float* __restrict__ A, int lda,
                                        const float* __restrict__ B, int ldb,
                                        int ktiles, u64 (&acc)[RM][RN]) {
    constexpr int TM = 16 * RM, TN = 16 * RN;
    const int tx = threadIdx.x & 15, ty = threadIdx.x >> 4;

    fill_t<TM>(sa, A, lda, 0);
    cp_commit();

    int buf = 0;
    for (int kt = 0; kt < ktiles; kt++) {
        cp_wait0();
        __syncthreads();
        if (kt + 1 < ktiles) {
            fill_t<TM>(sa + (buf ^ 1) * BUFSZ, A, lda, (kt + 1) * 64);
            fill_t<TN>(sb + (buf ^ 1) * BUFSZ, B, ldb, (kt + 1) * 64);
            cp_commit();
        }
        const float* as = sa + buf * BUFSZ;
        const float* bs = sb + buf * BUFSZ;
#pragma unroll
        for (int k4 = 0; k4 < 16; k4++) {
            ulonglong2 a2[RM], b2[RN];
#pragma unroll
            for (int im = 0; im < RM; im++)
                a2[im] = *reinterpret_cast<const ulonglong2*>(as + (ty + 16 * im) * SB + k4 * 4);
#pragma unroll
            for (int in = 0; in < RN; in++)
                b2[in] = *reinterpret_cast<const ulonglong2*>(bs + (tx + 16 * in) * SB + k4 * 4);
#pragma unroll
            for (int im = 0; im < RM; im++)
#pragma unroll
                for (int in = 0; in < RN; in++) {
                    ffma2(acc[im][in], a2[im].x, b2[in].x);
                    ffma2(acc[im][in], a2[im].y, b2[in].y);
                }
        }
        buf ^= 1;
    }
}

// ---------------------------------------------------------------------------
// Main persistent kernel (1 CTA/SM)
// ---------------------------------------------------------------------------
__global__ void __launch_bounds__(NTHREADS, 1)
pc_rnn_kernel(const float* __restrict__ x,
              const float* __restrict__ c_init,
              const float* __restrict__ h_init,
              const float* __restrict__ w_o,
              const float* __restrict__ b_o,
              const float* __restrict__ w_c,
              const float* __restrict__ w_r,
              const float* __restrict__ b_r,
              float* __restrict__ out) {
    __shared__ float s_a[2 * BUFSZ];   // A operand double buffer (17408 B)
    __shared__ float s_b[2 * BUFSZ];   // B operand double buffer (17408 B)

    const int bid = blockIdx.x;
    const int tid = threadIdx.x;
    const int tx  = tid & 15, ty = tid >> 4;
    const int gtid = bid * NTHREADS + tid;
    const int gstride = GRID * NTHREADS;

    // Tile maps (128 CTAs)
    const int rowA = (bid >> 4) * 32, colA = (bid & 15) * 32;  // A/C: 32x32
    const int rowB = (bid >> 4) * 32, colB = (bid & 15) * 16;  // B:   32x16
    const int rowD = (bid >> 2) * 8,  colD = (bid & 3) * 16;   // D:   8x16

    // ---- init state + weight transposes (fresh every launch/replay) ----
    for (int i = gtid; i < BATCH * HID; i += gstride) {
        float h = h_init[i];
        g_h[i]  = h;
        g_th[i] = tanhf(h);
    }
    for (int i = gtid; i < BATCH * CAUS; i += gstride)
        g_c[i] = c_init[i];
    for (int i = gtid; i < HID * OUTD; i += gstride) {   // woT[i][o] = w_o[o][i]
        int hh = i >> 8, o = i & (OUTD - 1);
        g_woT[i] = w_o[o * HID + hh];
    }
    for (int i = gtid; i < CAUS * HID; i += gstride) {   // wcT[c][i] = w_c[i][c]
        int c = i >> 9, hh = i & (HID - 1);
        g_wcT[i] = w_c[hh * CAUS + c];
    }
    __syncthreads();
    fill_t<32>(s_b, w_r + colA * HID, HID, 0);   // prefetch phase-A weights
    cp_commit();
    barrier_core();

    for (int t = 0; t < SEQ; t++) {
        // ---- Phase A: h_prior = 0.9*h + 0.1*(th@Wr^T + c@Wc^T + b_r); tp ----
        {
            u64 acc[2][2] = {};
            gemm_ss<2, 2>(s_a, s_b, g_th + rowA * HID, HID,
                          w_r + colA * HID, HID, HID / 64, acc);
            // c @ Wc^T part: single k-tile; fill both operands into buffer 0
            // (stragglers from the loop above only read buffer 1 -> safe)
            fill_t<32>(s_a, g_c + rowA * CAUS, CAUS, 0);
            fill_t<32>(s_b, w_c + colA * CAUS, CAUS, 0);
            cp_commit();
            cp_wait0();
            __syncthreads();
#pragma unroll
            for (int k4 = 0; k4 < 16; k4++) {
                ulonglong2 a2[2], b2[2];
#pragma unroll
                for (int im = 0; im < 2; im++)
                    a2[im] = *reinterpret_cast<const ulonglong2*>(s_a + (ty + 16 * im) * SB + k4 * 4);
#pragma unroll
                for (int in = 0; in < 2; in++)
                    b2[in] = *reinterpret_cast<const ulonglong2*>(s_b + (tx + 16 * in) * SB + k4 * 4);
#pragma unroll
                for (int im = 0; im < 2; im++)
#pragma unroll
                    for (int in = 0; in < 2; in++) {
                        ffma2(acc[im][in], a2[im].x, b2[in].x);
                        ffma2(acc[im][in], a2[im].y, b2[in].y);
                    }
            }
#pragma unroll
            for (int im = 0; im < 2; im++)
#pragma unroll
                for (int in = 0; in < 2; in++) {
                    int r   = rowA + ty + 16 * im;
                    int ci  = colA + tx + 16 * in;
                    int idx = r * HID + ci;
                    float hp = 0.9f * g_h[idx] + 0.1f * (fsum2(acc[im][in]) + b_r[ci]);
                    g_hp[idx] = hp;
                    g_tp[idx] = tanhf(hp);
                }
        }
        __syncthreads();                              // all buffer-0 readers done
        fill_t<16>(s_b, w_o + colB * HID, HID, 0);    // prefetch phase-B weights
        cp_commit();
        barrier_core();

        // ---- Phase B: err = tp@Wo^T + b_o - x_t  (streamed to out too) ----
        {
            u64 acc[2][1] = {};
            gemm_ss<2, 1>(s_a, s_b, g_tp + rowB * HID, HID,
                          w_o + colB * HID, HID, HID / 64, acc);
#pragma unroll
            for (int im = 0; im < 2; im++) {
                int r  = rowB + ty + 16 * im;
                int o  = colB + tx;
                int xi = (t * BATCH + r) * OUTD + o;
                float e = fsum2(acc[im][0]) + b_o[o] - x[xi];
                g_err[r * OUTD + o] = e;
                out[xi] = e;
            }
        }
        __syncthreads();
        fill_t<32>(s_b, g_woT + colA * OUTD, OUTD, 0);  // prefetch phase-C weights
        cp_commit();
        barrier_core();

        // ---- Phase C: g = err@woT; eh = 0.1*(1-tp^2)*g; h_post; th ----
        {
            u64 acc[2][2] = {};
            gemm_ss<2, 2>(s_a, s_b, g_err + rowA * OUTD, OUTD,
                          g_woT + colA * OUTD, OUTD, OUTD / 64, acc);
#pragma unroll
            for (int im = 0; im < 2; im++)
#pragma unroll
                for (int in = 0; in < 2; in++) {
                    int r   = rowA + ty + 16 * im;
                    int ci  = colA + tx + 16 * in;
                    int idx = r * HID + ci;
                    float tp = g_tp[idx];
                    float eh = 0.1f * (1.0f - tp * tp) * fsum2(acc[im][in]);
                    float hpost = g_hp[idx] - eh;
                    g_eh[idx] = eh;
                    g_h[idx]  = hpost;
                    g_th[idx] = tanhf(hpost);
                }
        }
        __syncthreads();
        fill_t<16>(s_b, g_wcT + colD * HID, HID, 0);    // prefetch phase-D weights
        cp_commit();
        barrier_core();

        // ---- Phase D: c -= 0.1 * (eh @ Wc)  (via wcT); A staged too ----
        {
            fill_t<8>(s_a, g_eh + rowD * HID, HID, 0);
            cp_commit();
            u64 accD = 0ull;
            int buf = 0;
            for (int kt = 0; kt < 8; kt++) {
                cp_wait0();
                __syncthreads();
                if (kt < 7) {
                    fill_t<8>(s_a + (buf ^ 1) * BUFSZ, g_eh + rowD * HID, HID, (kt + 1) * 64);
                    fill_t<16>(s_b + (buf ^ 1) * BUFSZ, g_wcT + colD * HID, HID, (kt + 1) * 64);
                    cp_commit();
                }
                if (tid < 128) {
                    const float* as = s_a + buf * BUFSZ + (ty & 7) * SB;
                    const float* bs = s_b + buf * BUFSZ + tx * SB;
#pragma unroll
                    for (int k4 = 0; k4 < 16; k4++) {
                        ulonglong2 a = *reinterpret_cast<const ulonglong2*>(as + k4 * 4);
                        ulonglong2 b = *reinterpret_cast<const ulonglong2*>(bs + k4 * 4);
                        ffma2(accD, a.x, b.x);
                        ffma2(accD, a.y, b.y);
                    }
                }
                buf ^= 1;
            }
            if (tid < 128)
                g_c[(rowD + (ty & 7)) * CAUS + colD + tx] -= 0.1f * fsum2(accD);
        }
        __syncthreads();
        fill_t<32>(s_b, w_r + colA * HID, HID, 0);      // prefetch next step's A
        cp_commit();
        barrier_core();
    }
}

// ---------------------------------------------------------------------------
// Launch: single graph-capturable kernel node, no allocation.
// Inputs (metadata order): x, c_init, h_init, w_o, b_o, w_c, w_r, b_r
// ---------------------------------------------------------------------------
extern "C" void kernel_launch(void* const* d_in, const int* in_sizes, int n_in,
                              void* d_out, int out_size) {
    const float* x      = (const float*)d_in[0];
    const float* c_init = (const float*)d_in[1];
    const float* h_init = (const float*)d_in[2];
    const float* w_o    = (const float*)d_in[3];
    const float* b_o    = (const float*)d_in[4];
    const float* w_c    = (const float*)d_in[5];
    const float* w_r    = (const float*)d_in[6];
    const float* b_r    = (const float*)d_in[7];
    float* out = (float*)d_out;

    pc_rnn_kernel<<<GRID, NTHREADS>>>(x, c_init, h_init, w_o, b_o, w_c, w_r, b_r, out);
}